// round 7
// baseline (speedup 1.0000x reference)
#include <cuda_runtime.h>
#include <cuda_bf16.h>
#include <cstdint>
#include <cfloat>

// Problem constants
#define NN 65536
#define DD 128
#define MM 8
#define KK 256

#define BM      128
#define THREADS 512            // 16 warps: wr = wid&3 (32-row group), wc = wid>>2 (64-col group)

// smem strides (elements)
#define CB_STRIDE 136          // bf16 codebook row stride
#define RB_STRIDE 136          // bf16 residual row stride

// smem layout (byte offsets)
#define SM_CB_B    0                                   // 256*136*2 = 69632
#define SM_RB_B    69632                               // 128*136*2 = 34816
#define SM_CSQ_B   104448                              // 256 f
#define SM_RSS_B   105472                              // 128 f
#define SM_CUT_B   105984                              // 128 f
#define SM_MINB_B  106496                              // 128*4 u64 = 4096
#define SM_CAND_B  110592                              // 128 u64 = 1024
#define SM_BYTES   111616

// margin coefficient: >= 3x worst-case bf16 screen error bound (validated rel_err=0.0 in R5)
#define MARG_COEF 0.05f

__device__ __forceinline__ uint32_t ford(float f) {
    uint32_t u = __float_as_uint(f);
    return (u & 0x80000000u) ? ~u : (u | 0x80000000u);
}
__device__ __forceinline__ uint32_t bf16x2_of(float lo, float hi) {
    uint32_t r;  // first source operand -> upper half
    asm("cvt.rn.bf16x2.f32 %0, %1, %2;" : "=r"(r) : "f"(hi), "f"(lo));
    return r;
}
__device__ __forceinline__ void mma_bf16(float& c0, float& c1, float& c2, float& c3,
                                         uint32_t a0, uint32_t a1, uint32_t a2, uint32_t a3,
                                         uint32_t b0, uint32_t b1) {
    asm volatile("mma.sync.aligned.m16n8k16.row.col.f32.bf16.bf16.f32 "
                 "{%0,%1,%2,%3}, {%4,%5,%6,%7}, {%8,%9}, {%0,%1,%2,%3};"
                 : "+f"(c0), "+f"(c1), "+f"(c2), "+f"(c3)
                 : "r"(a0), "r"(a1), "r"(a2), "r"(a3), "r"(b0), "r"(b1));
}

// exact fp32 csq (reference summation order) + per-stage max ||c||, computed once
__device__ float g_csq[MM][KK];
__device__ float g_cmax[MM];

__global__ void csq_prep_kernel(const float* __restrict__ cb) {
    int st = blockIdx.x;
    int k  = threadIdx.x;                  // 256 threads
    const float* row = cb + ((size_t)st * KK + k) * DD;
    float s = 0.f;
    for (int d = 0; d < DD; ++d) { float v = row[d]; s = fmaf(v, v, s); }
    g_csq[st][k] = s;
    __shared__ float red[KK];
    red[k] = s;
    __syncthreads();
    for (int off = 128; off > 0; off >>= 1) {
        if (k < off) red[k] = fmaxf(red[k], red[k + off]);
        __syncthreads();
    }
    if (k == 0) g_cmax[st] = sqrtf(red[0]);
}

__global__ __launch_bounds__(THREADS, 1)
void rq_stage_kernel(const float* __restrict__ x,
                     const float* __restrict__ C,       // stage codebook (K, D) fp32
                     float* __restrict__ codes,
                     float* __restrict__ side,
                     float* __restrict__ xrecon,
                     int stage)
{
    extern __shared__ char smem[];
    __nv_bfloat16* cbB  = (__nv_bfloat16*)(smem + SM_CB_B);
    __nv_bfloat16* resB = (__nv_bfloat16*)(smem + SM_RB_B);
    float*         csq  = (float*)(smem + SM_CSQ_B);
    float*         rss  = (float*)(smem + SM_RSS_B);
    float*         cut  = (float*)(smem + SM_CUT_B);
    unsigned long long* minb = (unsigned long long*)(smem + SM_MINB_B);
    unsigned long long* cand = (unsigned long long*)(smem + SM_CAND_B);

    const int tid  = threadIdx.x;
    const int wid  = tid >> 5;
    const int lane = tid & 31;
    const int rowBase = blockIdx.x * BM;

    const float* prev = (stage == 0) ? nullptr
                                     : (side + (size_t)(stage - 1) * NN * DD);

    // ---- codebook fp32 -> bf16 smem (row-major, stride 136); csq; cand init ----
    #pragma unroll
    for (int j = 0; j < (KK * DD / 2) / THREADS; ++j) {   // 32 pairs/thread
        int idx2 = tid + j * THREADS;
        int k = idx2 >> 6;            // 64 pairs per codeword row
        int dp = idx2 & 63;
        float2 v = *(const float2*)(C + (size_t)k * DD + dp * 2);
        *(uint32_t*)(cbB + k * CB_STRIDE + dp * 2) = bf16x2_of(v.x, v.y);
    }
    if (tid < KK) csq[tid] = g_csq[stage][tid];
    if (tid < BM) cand[tid] = ~0ull;

    // ---- residual tile: bf16 row-major (mma A) + per-row rss (exact fp32) ----
    {
        int r  = tid >> 2;
        int c0 = (tid & 3) * 32;
        const float* xrow = x + (size_t)(rowBase + r) * DD + c0;
        const float* prow = prev ? prev + (size_t)(rowBase + r) * DD + c0 : nullptr;
        float part = 0.f;
        #pragma unroll
        for (int j = 0; j < 32; j += 4) {
            float4 xv = *(const float4*)(xrow + j);
            float4 pv = prow ? *(const float4*)(prow + j) : make_float4(0.f,0.f,0.f,0.f);
            float r0 = xv.x - pv.x, r1 = xv.y - pv.y;
            float r2 = xv.z - pv.z, r3 = xv.w - pv.w;
            *(uint32_t*)(resB + r * RB_STRIDE + c0 + j)     = bf16x2_of(r0, r1);
            *(uint32_t*)(resB + r * RB_STRIDE + c0 + j + 2) = bf16x2_of(r2, r3);
            part = fmaf(r0, r0, part); part = fmaf(r1, r1, part);
            part = fmaf(r2, r2, part); part = fmaf(r3, r3, part);
        }
        part += __shfl_xor_sync(0xffffffffu, part, 1);
        part += __shfl_xor_sync(0xffffffffu, part, 2);
        if ((tid & 3) == 0) rss[r] = part;
    }
    __syncthreads();

    const int wr = wid & 3;           // row group: rows wr*32 .. +31
    const int wc = wid >> 2;          // col group: cols wc*64 .. +63
    const int m_base  = wr * 32;
    const int n_base0 = wc * 64;
    const int qr = lane >> 2;         // 0..7
    const int qc = (lane & 3) * 2;    // 0,2,4,6

    // ---- PHASE 1: screen. 16-col chunks; acc folded immediately (16 live acc regs) ----
    unsigned long long bk[4];         // per-row best keys: index mt*2+h
    bk[0] = bk[1] = bk[2] = bk[3] = ~0ull;

    #pragma unroll
    for (int ch = 0; ch < 4; ++ch) {
        const int n_base = n_base0 + ch * 16;
        float acc[2][2][4];
        #pragma unroll
        for (int mt = 0; mt < 2; ++mt)
            #pragma unroll
            for (int nt = 0; nt < 2; ++nt)
                #pragma unroll
                for (int c = 0; c < 4; ++c) acc[mt][nt][c] = 0.f;

        #pragma unroll
        for (int ks = 0; ks < 8; ++ks) {
            const int k0 = ks * 16;
            uint32_t B[2][2];
            #pragma unroll
            for (int nt = 0; nt < 2; ++nt) {
                int n = n_base + nt * 8 + qr;
                B[nt][0] = *(const uint32_t*)(cbB + n * CB_STRIDE + k0 + qc);
                B[nt][1] = *(const uint32_t*)(cbB + n * CB_STRIDE + k0 + qc + 8);
            }
            uint32_t A[2][4];
            #pragma unroll
            for (int mt = 0; mt < 2; ++mt) {
                int m0 = m_base + mt * 16 + qr;
                A[mt][0] = *(const uint32_t*)(resB + m0 * RB_STRIDE + k0 + qc);
                A[mt][1] = *(const uint32_t*)(resB + (m0 + 8) * RB_STRIDE + k0 + qc);
                A[mt][2] = *(const uint32_t*)(resB + m0 * RB_STRIDE + k0 + qc + 8);
                A[mt][3] = *(const uint32_t*)(resB + (m0 + 8) * RB_STRIDE + k0 + qc + 8);
            }
            #pragma unroll
            for (int mt = 0; mt < 2; ++mt)
                #pragma unroll
                for (int nt = 0; nt < 2; ++nt)
                    mma_bf16(acc[mt][nt][0], acc[mt][nt][1], acc[mt][nt][2], acc[mt][nt][3],
                             A[mt][0], A[mt][1], A[mt][2], A[mt][3], B[nt][0], B[nt][1]);
        }
        // fold this chunk into per-row best keys
        #pragma unroll
        for (int mt = 0; mt < 2; ++mt)
            #pragma unroll
            for (int h = 0; h < 2; ++h) {
                int row = m_base + mt * 16 + h * 8 + qr;
                float rv = rss[row];
                unsigned long long b = bk[mt * 2 + h];
                #pragma unroll
                for (int nt = 0; nt < 2; ++nt)
                    #pragma unroll
                    for (int p = 0; p < 2; ++p) {
                        int k = n_base + nt * 8 + qc + p;
                        float d2 = __fadd_rn(
                            __fadd_rn(rv, __fmul_rn(-2.f, acc[mt][nt][h * 2 + p])), csq[k]);
                        unsigned long long key =
                            ((unsigned long long)ford(d2) << 32) | (unsigned)k;
                        if (key < b) b = key;
                    }
                bk[mt * 2 + h] = b;
            }
    }
    // quad-reduce (lanes of same row) and publish per-(row, 64-col group) minima
    #pragma unroll
    for (int i = 0; i < 4; ++i) {
        unsigned long long b = bk[i], o;
        o = __shfl_xor_sync(0xffffffffu, b, 1); if (o < b) b = o;
        o = __shfl_xor_sync(0xffffffffu, b, 2); if (o < b) b = o;
        int row = m_base + (i >> 1) * 16 + (i & 1) * 8 + qr;
        if ((lane & 3) == 0) minb[row * 4 + wc] = b;
    }
    __syncthreads();

    if (tid < BM) {
        unsigned long long m = minb[tid * 4];
        m = min(m, minb[tid * 4 + 1]);
        m = min(m, minb[tid * 4 + 2]);
        m = min(m, minb[tid * 4 + 3]);
        uint32_t ou = (uint32_t)(m >> 32);
        float amin = __uint_as_float((ou & 0x80000000u) ? (ou & 0x7fffffffu) : ~ou);
        cut[tid] = amin + MARG_COEF * sqrtf(rss[tid]) * g_cmax[stage];
    }
    __syncthreads();

    // ---- PHASE 2: recompute MMA per chunk; candidates within margin -> exact rescore ----
    #pragma unroll
    for (int ch = 0; ch < 4; ++ch) {
        const int n_base = n_base0 + ch * 16;
        float acc[2][2][4];
        #pragma unroll
        for (int mt = 0; mt < 2; ++mt)
            #pragma unroll
            for (int nt = 0; nt < 2; ++nt)
                #pragma unroll
                for (int c = 0; c < 4; ++c) acc[mt][nt][c] = 0.f;

        #pragma unroll
        for (int ks = 0; ks < 8; ++ks) {
            const int k0 = ks * 16;
            uint32_t B[2][2];
            #pragma unroll
            for (int nt = 0; nt < 2; ++nt) {
                int n = n_base + nt * 8 + qr;
                B[nt][0] = *(const uint32_t*)(cbB + n * CB_STRIDE + k0 + qc);
                B[nt][1] = *(const uint32_t*)(cbB + n * CB_STRIDE + k0 + qc + 8);
            }
            uint32_t A[2][4];
            #pragma unroll
            for (int mt = 0; mt < 2; ++mt) {
                int m0 = m_base + mt * 16 + qr;
                A[mt][0] = *(const uint32_t*)(resB + m0 * RB_STRIDE + k0 + qc);
                A[mt][1] = *(const uint32_t*)(resB + (m0 + 8) * RB_STRIDE + k0 + qc);
                A[mt][2] = *(const uint32_t*)(resB + m0 * RB_STRIDE + k0 + qc + 8);
                A[mt][3] = *(const uint32_t*)(resB + (m0 + 8) * RB_STRIDE + k0 + qc + 8);
            }
            #pragma unroll
            for (int mt = 0; mt < 2; ++mt)
                #pragma unroll
                for (int nt = 0; nt < 2; ++nt)
                    mma_bf16(acc[mt][nt][0], acc[mt][nt][1], acc[mt][nt][2], acc[mt][nt][3],
                             A[mt][0], A[mt][1], A[mt][2], A[mt][3], B[nt][0], B[nt][1]);
        }

        #pragma unroll
        for (int mt = 0; mt < 2; ++mt)
            #pragma unroll
            for (int h = 0; h < 2; ++h) {
                int row = m_base + mt * 16 + h * 8 + qr;
                float rv   = rss[row];
                float cutv = cut[row];
                #pragma unroll
                for (int nt = 0; nt < 2; ++nt)
                    #pragma unroll
                    for (int p = 0; p < 2; ++p) {
                        int k = n_base + nt * 8 + qc + p;
                        float d2a = __fadd_rn(
                            __fadd_rn(rv, __fmul_rn(-2.f, acc[mt][nt][h * 2 + p])), csq[k]);
                        if (d2a <= cutv) {
                            // exact rescore: rebuild res row from x/prev (identical sub +
                            // identical d-ascending fmaf chain => bit-exact vs reference path)
                            int n = rowBase + row;
                            const float4* xr = (const float4*)(x + (size_t)n * DD);
                            const float4* pr = prev ? (const float4*)(prev + (size_t)n * DD)
                                                    : nullptr;
                            const float4* cr = (const float4*)(C + (size_t)k * DD);
                            float a = 0.f;
                            for (int c = 0; c < 32; ++c) {
                                float4 xv = __ldg(xr + c);
                                float4 pv = pr ? __ldg(pr + c)
                                               : make_float4(0.f, 0.f, 0.f, 0.f);
                                float4 cv = __ldg(cr + c);
                                a = fmaf(xv.x - pv.x, cv.x, a);
                                a = fmaf(xv.y - pv.y, cv.y, a);
                                a = fmaf(xv.z - pv.z, cv.z, a);
                                a = fmaf(xv.w - pv.w, cv.w, a);
                            }
                            float t1  = __fadd_rn(rv, __fmul_rn(-2.0f, a));
                            float d2e = __fadd_rn(t1, csq[k]);
                            unsigned long long pk =
                                ((unsigned long long)ford(d2e) << 32) | (unsigned)k;
                            atomicMin(&cand[row], pk);
                        }
                    }
            }
    }
    __syncthreads();

    // ---- outputs: one-hot codes + recon (bit-exact recurrence), float4 stores ----
    const bool last = (stage == MM - 1);
    float* sstage = side + (size_t)stage * NN * DD;

    #pragma unroll
    for (int rr2 = 0; rr2 < 8; ++rr2) {
        int lrow = wid * 8 + rr2;
        int n    = rowBase + lrow;
        int bidx = (int)(cand[lrow] & 0xffffffffull);

        float4* crow_codes = (float4*)(codes + (size_t)n * (MM * KK) + (size_t)stage * KK);
        #pragma unroll
        for (int t = 0; t < 2; ++t) {
            int j  = lane + 32 * t;     // float4 index, 64 per row
            int k0 = j * 4;
            float4 v;
            v.x = (k0     == bidx) ? 1.0f : 0.0f;
            v.y = (k0 + 1 == bidx) ? 1.0f : 0.0f;
            v.z = (k0 + 2 == bidx) ? 1.0f : 0.0f;
            v.w = (k0 + 3 == bidx) ? 1.0f : 0.0f;
            crow_codes[j] = v;
        }

        const float4* prow  = prev ? (const float4*)(prev + (size_t)n * DD) : nullptr;
        const float4* cbrow = (const float4*)(C + (size_t)bidx * DD);
        float4* srow = (float4*)(sstage + (size_t)n * DD);
        float4* orow = (float4*)(xrecon + (size_t)n * DD);
        {
            float4 cv = __ldg(cbrow + lane);
            float4 pp = prow ? __ldg(prow + lane) : make_float4(0.f, 0.f, 0.f, 0.f);
            float4 v;
            v.x = __fadd_rn(pp.x, cv.x);
            v.y = __fadd_rn(pp.y, cv.y);
            v.z = __fadd_rn(pp.z, cv.z);
            v.w = __fadd_rn(pp.w, cv.w);
            srow[lane] = v;
            if (last) orow[lane] = v;
        }
    }
}

extern "C" void kernel_launch(void* const* d_in, const int* in_sizes, int n_in,
                              void* d_out, int out_size)
{
    (void)in_sizes; (void)n_in; (void)out_size;
    const float* x  = (const float*)d_in[0];            // (N, D)
    const float* cb = (const float*)d_in[1];            // (M, K, D)

    float* out    = (float*)d_out;
    float* xrecon = out;                                // (N, D)
    float* codes  = out + (size_t)NN * DD;              // (N, M, K)
    float* side   = codes + (size_t)NN * MM * KK;       // (M, N, D)

    cudaFuncSetAttribute(rq_stage_kernel,
                         cudaFuncAttributeMaxDynamicSharedMemorySize, SM_BYTES);

    csq_prep_kernel<<<MM, KK>>>(cb);

    const int grid = NN / BM;   // 512
    for (int i = 0; i < MM; ++i) {
        rq_stage_kernel<<<grid, THREADS, SM_BYTES>>>(
            x, cb + (size_t)i * KK * DD, codes, side, xrecon, i);
    }
}

// round 8
// speedup vs baseline: 6.0216x; 6.0216x over previous
#include <cuda_runtime.h>
#include <cuda_bf16.h>
#include <cstdint>
#include <cfloat>

// Problem constants
#define NN 65536
#define DD 128
#define MM 8
#define KK 256

#define BM      128
#define THREADS 512            // kernelA: 16 warps; wr = wid&3 (32-row), wc = wid>>2 (64-col)

// smem strides (bf16 elements)
#define CB_STRIDE 136
#define RB_STRIDE 136

// kernelA smem layout (bytes)
#define SM_CB_B    0                                   // 256*136*2 = 69632
#define SM_RB_B    69632                               // 128*136*2 = 34816
#define SM_BYTES_A 104448

// margin coefficient: >= 3x worst-case bf16 screen error bound (rel_err=0.0 in R5/R6)
#define MARG_COEF 0.05f

// 64MB scratch: raw fp32 dot products from the bf16 tensor-core screen, + per-row rss
__device__ float g_dot[(size_t)NN * KK];
__device__ float g_rss[NN];
__device__ float g_csq[MM][KK];
__device__ float g_cmax[MM];

__device__ __forceinline__ uint32_t ford(float f) {
    uint32_t u = __float_as_uint(f);
    return (u & 0x80000000u) ? ~u : (u | 0x80000000u);
}
__device__ __forceinline__ uint32_t bf16x2_of(float lo, float hi) {
    uint32_t r;  // first source operand -> upper half
    asm("cvt.rn.bf16x2.f32 %0, %1, %2;" : "=r"(r) : "f"(hi), "f"(lo));
    return r;
}
__device__ __forceinline__ void mma_bf16(float& c0, float& c1, float& c2, float& c3,
                                         uint32_t a0, uint32_t a1, uint32_t a2, uint32_t a3,
                                         uint32_t b0, uint32_t b1) {
    asm volatile("mma.sync.aligned.m16n8k16.row.col.f32.bf16.bf16.f32 "
                 "{%0,%1,%2,%3}, {%4,%5,%6,%7}, {%8,%9}, {%0,%1,%2,%3};"
                 : "+f"(c0), "+f"(c1), "+f"(c2), "+f"(c3)
                 : "r"(a0), "r"(a1), "r"(a2), "r"(a3), "r"(b0), "r"(b1));
}

__global__ void csq_prep_kernel(const float* __restrict__ cb) {
    int st = blockIdx.x;
    int k  = threadIdx.x;                  // 256 threads
    const float* row = cb + ((size_t)st * KK + k) * DD;
    float s = 0.f;
    for (int d = 0; d < DD; ++d) { float v = row[d]; s = fmaf(v, v, s); }
    g_csq[st][k] = s;
    __shared__ float red[KK];
    red[k] = s;
    __syncthreads();
    for (int off = 128; off > 0; off >>= 1) {
        if (k < off) red[k] = fmaxf(red[k], red[k + off]);
        __syncthreads();
    }
    if (k == 0) g_cmax[st] = sqrtf(red[0]);
}

// ---------------- kernel A: bf16 tensor-core screen -> g_dot, g_rss ----------------
__global__ __launch_bounds__(THREADS, 1)
void rq_screen_kernel(const float* __restrict__ x,
                      const float* __restrict__ C,     // stage codebook (K, D) fp32
                      const float* __restrict__ prev)  // side[stage-1] or null
{
    extern __shared__ char smem[];
    __nv_bfloat16* cbB  = (__nv_bfloat16*)(smem + SM_CB_B);
    __nv_bfloat16* resB = (__nv_bfloat16*)(smem + SM_RB_B);

    const int tid  = threadIdx.x;
    const int wid  = tid >> 5;
    const int lane = tid & 31;
    const int rowBase = blockIdx.x * BM;

    // codebook fp32 -> bf16 smem (row-major, stride 136)
    #pragma unroll
    for (int j = 0; j < (KK * DD / 2) / THREADS; ++j) {   // 32 pairs/thread
        int idx2 = tid + j * THREADS;
        int k = idx2 >> 6;
        int dp = idx2 & 63;
        float2 v = *(const float2*)(C + (size_t)k * DD + dp * 2);
        *(uint32_t*)(cbB + k * CB_STRIDE + dp * 2) = bf16x2_of(v.x, v.y);
    }

    // residual tile bf16 + exact-fp32 rss -> g_rss
    {
        int r  = tid >> 2;
        int c0 = (tid & 3) * 32;
        const float* xrow = x + (size_t)(rowBase + r) * DD + c0;
        const float* prow = prev ? prev + (size_t)(rowBase + r) * DD + c0 : nullptr;
        float part = 0.f;
        #pragma unroll
        for (int j = 0; j < 32; j += 4) {
            float4 xv = *(const float4*)(xrow + j);
            float4 pv = prow ? *(const float4*)(prow + j) : make_float4(0.f,0.f,0.f,0.f);
            float r0 = xv.x - pv.x, r1 = xv.y - pv.y;
            float r2 = xv.z - pv.z, r3 = xv.w - pv.w;
            *(uint32_t*)(resB + r * RB_STRIDE + c0 + j)     = bf16x2_of(r0, r1);
            *(uint32_t*)(resB + r * RB_STRIDE + c0 + j + 2) = bf16x2_of(r2, r3);
            part = fmaf(r0, r0, part); part = fmaf(r1, r1, part);
            part = fmaf(r2, r2, part); part = fmaf(r3, r3, part);
        }
        part += __shfl_xor_sync(0xffffffffu, part, 1);
        part += __shfl_xor_sync(0xffffffffu, part, 2);
        if ((tid & 3) == 0) g_rss[rowBase + r] = part;
    }
    __syncthreads();

    const int wr = wid & 3;
    const int wc = wid >> 2;
    const int m_base  = wr * 32;
    const int n_base0 = wc * 64;
    const int qr = lane >> 2;
    const int qc = (lane & 3) * 2;

    // chunked GEMM: 16-col chunks, 16 live accumulators; stream dots to scratch
    #pragma unroll 1
    for (int ch = 0; ch < 4; ++ch) {
        const int n_base = n_base0 + ch * 16;
        float acc[2][2][4];
        #pragma unroll
        for (int mt = 0; mt < 2; ++mt)
            #pragma unroll
            for (int nt = 0; nt < 2; ++nt)
                #pragma unroll
                for (int c = 0; c < 4; ++c) acc[mt][nt][c] = 0.f;

        #pragma unroll 1
        for (int ks = 0; ks < 8; ++ks) {
            const int k0 = ks * 16;
            uint32_t B[2][2];
            #pragma unroll
            for (int nt = 0; nt < 2; ++nt) {
                int n = n_base + nt * 8 + qr;
                B[nt][0] = *(const uint32_t*)(cbB + n * CB_STRIDE + k0 + qc);
                B[nt][1] = *(const uint32_t*)(cbB + n * CB_STRIDE + k0 + qc + 8);
            }
            uint32_t A[2][4];
            #pragma unroll
            for (int mt = 0; mt < 2; ++mt) {
                int m0 = m_base + mt * 16 + qr;
                A[mt][0] = *(const uint32_t*)(resB + m0 * RB_STRIDE + k0 + qc);
                A[mt][1] = *(const uint32_t*)(resB + (m0 + 8) * RB_STRIDE + k0 + qc);
                A[mt][2] = *(const uint32_t*)(resB + m0 * RB_STRIDE + k0 + qc + 8);
                A[mt][3] = *(const uint32_t*)(resB + (m0 + 8) * RB_STRIDE + k0 + qc + 8);
            }
            #pragma unroll
            for (int mt = 0; mt < 2; ++mt)
                #pragma unroll
                for (int nt = 0; nt < 2; ++nt)
                    mma_bf16(acc[mt][nt][0], acc[mt][nt][1], acc[mt][nt][2], acc[mt][nt][3],
                             A[mt][0], A[mt][1], A[mt][2], A[mt][3], B[nt][0], B[nt][1]);
        }

        #pragma unroll
        for (int mt = 0; mt < 2; ++mt)
            #pragma unroll
            for (int h = 0; h < 2; ++h) {
                int row = m_base + mt * 16 + h * 8 + qr;
                #pragma unroll
                for (int nt = 0; nt < 2; ++nt) {
                    size_t base = (size_t)(rowBase + row) * KK + (n_base + nt * 8 + qc);
                    float2 v = make_float2(acc[mt][nt][h * 2], acc[mt][nt][h * 2 + 1]);
                    *(float2*)(g_dot + base) = v;
                }
            }
    }
}

// ---------------- kernel B: selection + exact rescue + outputs (1 warp / row) ----------------
#define SEL_WARPS 8
__global__ __launch_bounds__(SEL_WARPS * 32)
void rq_select_kernel(const float* __restrict__ x,
                      const float* __restrict__ C,
                      const float* __restrict__ prev,
                      float* __restrict__ codes,
                      float* __restrict__ sideStage,
                      float* __restrict__ xrecon,
                      int stage, int last)
{
    const int lane = threadIdx.x & 31;
    const int n = blockIdx.x * SEL_WARPS + (threadIdx.x >> 5);   // row

    const float rv = g_rss[n];
    const float* dotrow = g_dot + (size_t)n * KK;
    const float* csq = g_csq[stage];

    // d2 for 8 ks: slots 0-3 -> k=lane*4+e, slots 4-7 -> k=128+lane*4+(e-4)
    float4 da = *(const float4*)(dotrow + lane * 4);
    float4 db = *(const float4*)(dotrow + 128 + lane * 4);
    float4 ca = *(const float4*)(csq + lane * 4);
    float4 cb4 = *(const float4*)(csq + 128 + lane * 4);
    float d2[8];
    d2[0] = __fadd_rn(__fadd_rn(rv, __fmul_rn(-2.f, da.x)), ca.x);
    d2[1] = __fadd_rn(__fadd_rn(rv, __fmul_rn(-2.f, da.y)), ca.y);
    d2[2] = __fadd_rn(__fadd_rn(rv, __fmul_rn(-2.f, da.z)), ca.z);
    d2[3] = __fadd_rn(__fadd_rn(rv, __fmul_rn(-2.f, da.w)), ca.w);
    d2[4] = __fadd_rn(__fadd_rn(rv, __fmul_rn(-2.f, db.x)), cb4.x);
    d2[5] = __fadd_rn(__fadd_rn(rv, __fmul_rn(-2.f, db.y)), cb4.y);
    d2[6] = __fadd_rn(__fadd_rn(rv, __fmul_rn(-2.f, db.z)), cb4.z);
    d2[7] = __fadd_rn(__fadd_rn(rv, __fmul_rn(-2.f, db.w)), cb4.w);

    // warp packed-key argmin on approx d2
    unsigned long long best = ~0ull;
    #pragma unroll
    for (int s = 0; s < 8; ++s) {
        int k = (s < 4) ? (lane * 4 + s) : (128 + lane * 4 + s - 4);
        unsigned long long key = ((unsigned long long)ford(d2[s]) << 32) | (unsigned)k;
        if (key < best) best = key;
    }
    #pragma unroll
    for (int off = 16; off > 0; off >>= 1) {
        unsigned long long o = __shfl_xor_sync(0xffffffffu, best, off);
        if (o < best) best = o;
    }
    uint32_t ou = (uint32_t)(best >> 32);
    float amin = __uint_as_float((ou & 0x80000000u) ? (ou & 0x7fffffffu) : ~ou);
    float cutv = amin + MARG_COEF * sqrtf(rv) * g_cmax[stage];

    // candidate census
    int myflags = 0;
    #pragma unroll
    for (int s = 0; s < 8; ++s)
        if (d2[s] <= cutv) myflags |= 1 << s;
    int tot = __popc(myflags);
    #pragma unroll
    for (int off = 16; off > 0; off >>= 1)
        tot += __shfl_xor_sync(0xffffffffu, tot, off);

    int bidx;
    if (tot == 1) {
        // singleton candidate set provably equals the true argmin
        bidx = (int)(best & 0xffffffffull);
    } else {
        // exact fp32 rescore (identical d-ascending fmaf chain as prior passing rounds)
        unsigned long long bw = ~0ull;
        const float4* xr = (const float4*)(x + (size_t)n * DD);
        const float4* pr = prev ? (const float4*)(prev + (size_t)n * DD) : nullptr;
        #pragma unroll 1
        for (int s = 0; s < 8; ++s) {
            if ((myflags >> s) & 1) {
                int k = (s < 4) ? (lane * 4 + s) : (128 + lane * 4 + s - 4);
                const float4* cr = (const float4*)(C + (size_t)k * DD);
                float a = 0.f;
                #pragma unroll 1
                for (int c = 0; c < 32; ++c) {
                    float4 xv = __ldg(xr + c);
                    float4 pv = pr ? __ldg(pr + c) : make_float4(0.f, 0.f, 0.f, 0.f);
                    float4 cv = __ldg(cr + c);
                    a = fmaf(xv.x - pv.x, cv.x, a);
                    a = fmaf(xv.y - pv.y, cv.y, a);
                    a = fmaf(xv.z - pv.z, cv.z, a);
                    a = fmaf(xv.w - pv.w, cv.w, a);
                }
                float t1  = __fadd_rn(rv, __fmul_rn(-2.0f, a));
                float d2e = __fadd_rn(t1, csq[k]);
                unsigned long long pk = ((unsigned long long)ford(d2e) << 32) | (unsigned)k;
                if (pk < bw) bw = pk;
            }
        }
        #pragma unroll
        for (int off = 16; off > 0; off >>= 1) {
            unsigned long long o = __shfl_xor_sync(0xffffffffu, bw, off);
            if (o < bw) bw = o;
        }
        bidx = (int)(bw & 0xffffffffull);
    }

    // outputs: one-hot codes row + recon row (bit-exact recurrence)
    float4* crow = (float4*)(codes + (size_t)n * (MM * KK) + (size_t)stage * KK);
    #pragma unroll
    for (int t = 0; t < 2; ++t) {
        int j  = lane + 32 * t;
        int k0 = j * 4;
        float4 v;
        v.x = (k0     == bidx) ? 1.0f : 0.0f;
        v.y = (k0 + 1 == bidx) ? 1.0f : 0.0f;
        v.z = (k0 + 2 == bidx) ? 1.0f : 0.0f;
        v.w = (k0 + 3 == bidx) ? 1.0f : 0.0f;
        crow[j] = v;
    }
    {
        float4 cv = __ldg((const float4*)(C + (size_t)bidx * DD) + lane);
        float4 pp = prev ? __ldg((const float4*)(prev + (size_t)n * DD) + lane)
                         : make_float4(0.f, 0.f, 0.f, 0.f);
        float4 v;
        v.x = __fadd_rn(pp.x, cv.x);
        v.y = __fadd_rn(pp.y, cv.y);
        v.z = __fadd_rn(pp.z, cv.z);
        v.w = __fadd_rn(pp.w, cv.w);
        ((float4*)(sideStage + (size_t)n * DD))[lane] = v;
        if (last) ((float4*)(xrecon + (size_t)n * DD))[lane] = v;
    }
}

extern "C" void kernel_launch(void* const* d_in, const int* in_sizes, int n_in,
                              void* d_out, int out_size)
{
    (void)in_sizes; (void)n_in; (void)out_size;
    const float* x  = (const float*)d_in[0];            // (N, D)
    const float* cb = (const float*)d_in[1];            // (M, K, D)

    float* out    = (float*)d_out;
    float* xrecon = out;                                // (N, D)
    float* codes  = out + (size_t)NN * DD;              // (N, M, K)
    float* side   = codes + (size_t)NN * MM * KK;       // (M, N, D)

    cudaFuncSetAttribute(rq_screen_kernel,
                         cudaFuncAttributeMaxDynamicSharedMemorySize, SM_BYTES_A);

    csq_prep_kernel<<<MM, KK>>>(cb);

    const int gridA = NN / BM;                 // 512
    const int gridB = NN / SEL_WARPS;          // 8192
    for (int i = 0; i < MM; ++i) {
        const float* prev = (i == 0) ? nullptr : (side + (size_t)(i - 1) * NN * DD);
        const float* Ci   = cb + (size_t)i * KK * DD;
        rq_screen_kernel<<<gridA, THREADS, SM_BYTES_A>>>(x, Ci, prev);
        rq_select_kernel<<<gridB, SEL_WARPS * 32>>>(
            x, Ci, prev, codes, side + (size_t)i * NN * DD, xrecon, i, i == MM - 1);
    }
}